// round 9
// baseline (speedup 1.0000x reference)
#include <cuda_runtime.h>
#include <cstddef>

typedef unsigned long long ull;

#define B_   512
#define S_   2048
#define H_   64
#define GB   4                  // batch per CTA
#define NCTA (B_ / GB)          // 128 CTAs -> 1 per SM

// Scratch (sanctioned __device__ globals): two full pre-activation buffers.
__device__ float g_xp1[(size_t)B_ * S_ * 256];
__device__ float g_xp2[(size_t)B_ * S_ * 256];
__device__ float g_hlast[B_ * H_];

struct alignas(16) UPair { ull lo, hi; };

__device__ __forceinline__ float ex2a(float x) {
    float y; asm("ex2.approx.ftz.f32 %0, %1;" : "=f"(y) : "f"(x)); return y;
}
__device__ __forceinline__ float rcpa(float x) {
    float y; asm("rcp.approx.ftz.f32 %0, %1;" : "=f"(y) : "f"(x)); return y;
}
__device__ __forceinline__ float sigf(float z) {
    return rcpa(1.0f + ex2a(-1.4426950408889634f * z));
}
__device__ __forceinline__ float tanha(float z) {
    return 1.0f - 2.0f * rcpa(1.0f + ex2a(2.8853900817779268f * z));
}
__device__ __forceinline__ ull ffma2(ull a, ull b, ull c) {
    ull d;
    asm("fma.rn.f32x2 %0, %1, %2, %3;" : "=l"(d) : "l"(a), "l"(b), "l"(c));
    return d;
}
__device__ __forceinline__ float hadd2(ull v) {
    float lo, hi;
    asm("mov.b64 {%0, %1}, %2;" : "=f"(lo), "=f"(hi) : "l"(v));
    return lo + hi;
}
__device__ __forceinline__ ull pack2(float lo, float hi) {
    ull d; asm("mov.b64 %0, {%1, %2};" : "=l"(d) : "f"(lo), "f"(hi)); return d;
}
__device__ __forceinline__ float shflb(float v, int x) {
    float r;
    asm("shfl.sync.bfly.b32 %0, %1, %2, 0x1F, 0xFFFFFFFF;"
        : "=r"(*(unsigned*)&r) : "r"(*(unsigned*)&v), "r"(x));
    return r;
}

// ---------------------------------------------------------------------------
// Fused kernel: LSTM layer recurrence + NEXT layer's input projection.
// 512 threads, 16 warps, ONE barrier per step.
// Lane map: g = l&3 (gate), uu = (w&7)*8 + (l>>2), bp = (w>>3)*2, row = uu+64g.
// Thread computes: gate row `row` for batches (bp, bp+1), AND next-layer
// projection row `row` for the same batches (shares the h UPair loads).
// xp results staged in smem (double-buffered), flushed coalesced with 2-step
// lag; xp_{t-1} is computed in iteration t from the same h_{t-1} the gates use.
// L0=true: gates take x (dim 4) inline + bias; else z from xin (bias folded).
// ---------------------------------------------------------------------------
template <bool L0>
__global__ void __launch_bounds__(512, 1)
fused_kernel(const float* __restrict__ xin,   // L0: x[B][S][4]; else z[B][S][256]
             const float* __restrict__ Wih,   // this layer Wih (L0 only) [256][4]
             const float* __restrict__ Whh,   // this layer [256][64]
             const float* __restrict__ bih,   // L0 only
             const float* __restrict__ bhh,   // L0 only
             const float* __restrict__ WihN,  // NEXT layer Wih [256][64]
             const float* __restrict__ bihN,
             const float* __restrict__ bhhN,
             float* __restrict__ xpo)         // next-layer z out [B][S][256]
{
    __shared__ __align__(16) float hb[2][GB * H_];     // h ping-pong
    __shared__ __align__(16) float xps[2][GB * 256];   // xp staging ping-pong

    const int tid = threadIdx.x;
    const int w   = tid >> 5;
    const int l   = tid & 31;
    const int g   = l & 3;                  // gate: 0=i 1=f 2=g 3=o
    const int q   = g >> 1;                 // 0: holds i/f pair; 1: g/o pair
    const int glo = g & 1;
    const int uu  = (w & 7) * 8 + (l >> 2); // 0..63
    const int bp  = (w >> 3) * 2;           // 0 or 2
    const int b0  = blockIdx.x * GB;
    const int row = uu + g * 64;

    // this layer's recurrent row + next layer's projection row (registers)
    ull wg[32], wx[32];
    {
        const ull* pg = reinterpret_cast<const ull*>(Whh + row * H_);
        const ull* px = reinterpret_cast<const ull*>(WihN + row * H_);
#pragma unroll
        for (int k = 0; k < 32; ++k) { wg[k] = pg[k]; wx[k] = px[k]; }
    }
    const float bxr = bihN[row] + bhhN[row];

    // gate activation params: g==2 -> tanh, else sigmoid (uniform stream)
    const float mA = (g == 2) ? 2.8853900817779268f : -1.4426950408889634f;
    const float sA = (g == 2) ? -2.0f : 1.0f;
    const float dA = (g == 2) ? 1.0f : 0.0f;

    float biasr = 0.0f;
    ull wi0 = 0, wi1 = 0;
    const float4 *xq0 = nullptr, *xq1 = nullptr;
    const float  *zq0 = nullptr, *zq1 = nullptr;
    float4 x0, x1; float za0 = 0.0f, za1 = 0.0f;

    if constexpr (L0) {
        biasr = bih[row] + bhh[row];
        const ull* wi = reinterpret_cast<const ull*>(Wih + row * 4);
        wi0 = wi[0]; wi1 = wi[1];
        xq0 = reinterpret_cast<const float4*>(xin + (size_t)(b0 + bp) * S_ * 4);
        xq1 = reinterpret_cast<const float4*>(xin + (size_t)(b0 + bp + 1) * S_ * 4);
        x0 = xq0[0]; x1 = xq1[0];
    } else {
        zq0 = xin + (size_t)(b0 + bp) * S_ * 256 + row;
        zq1 = xin + (size_t)(b0 + bp + 1) * S_ * 256 + row;
        za0 = zq0[0]; za1 = zq1[0];
    }

    float c0 = 0.0f, c1 = 0.0f;
    for (int i = tid; i < GB * H_; i += 512) hb[1][i] = 0.0f;
    __syncthreads();

    for (int t = 0; t < S_; ++t) {
        const int rb = (t + 1) & 1;   // read buffer: h_{t-1}, xp_{t-2}
        const int wbuf = t & 1;       // write buffer: h_t, xp_{t-1}
        const UPair* v0 = reinterpret_cast<const UPair*>(hb[rb] + bp * H_);
        const UPair* v1 = reinterpret_cast<const UPair*>(hb[rb] + (bp + 1) * H_);

        // prefetch next step's input
        float4 nx0, nx1; float nza0 = 0.0f, nza1 = 0.0f;
        if (t + 1 < S_) {
            if constexpr (L0) { nx0 = xq0[t + 1]; nx1 = xq1[t + 1]; }
            else {
                const size_t o = (size_t)(t + 1) * 256;
                nza0 = zq0[o]; nza1 = zq1[o];
            }
        }

        // gate dot + xp dot share the h loads: each UPair feeds 8 FFMA2
        ull A0 = 0ull, A1 = 0ull, X0 = 0ull, X1 = 0ull;
#pragma unroll
        for (int k = 0; k < 16; ++k) {
            const ull gl = wg[2 * k], gh = wg[2 * k + 1];
            const ull xl = wx[2 * k], xh = wx[2 * k + 1];
            const UPair a0 = v0[k];
            const UPair a1 = v1[k];
            A0 = ffma2(gl, a0.lo, A0); A0 = ffma2(gh, a0.hi, A0);
            A1 = ffma2(gl, a1.lo, A1); A1 = ffma2(gh, a1.hi, A1);
            X0 = ffma2(xl, a0.lo, X0); X0 = ffma2(xh, a0.hi, X0);
            X1 = ffma2(xl, a1.lo, X1); X1 = ffma2(xh, a1.hi, X1);
        }

        float zA0, zA1;
        if constexpr (L0) {
            A0 = ffma2(wi0, pack2(x0.x, x0.y), A0); A0 = ffma2(wi1, pack2(x0.z, x0.w), A0);
            A1 = ffma2(wi0, pack2(x1.x, x1.y), A1); A1 = ffma2(wi1, pack2(x1.z, x1.w), A1);
            zA0 = hadd2(A0) + biasr;
            zA1 = hadd2(A1) + biasr;
        } else {
            zA0 = hadd2(A0) + za0;
            zA1 = hadd2(A1) + za1;
        }

        // stage xp_{t-1} = WihN . h_{t-1} + biasN  (garbage at t==0, never read)
        xps[wbuf][bp * 256 + row]       = hadd2(X0) + bxr;
        xps[wbuf][(bp + 1) * 256 + row] = hadd2(X1) + bxr;

        // activation (param-unified sigmoid/tanh)
        const float a0 = sA * rcpa(1.0f + ex2a(mA * zA0)) + dA;
        const float a1 = sA * rcpa(1.0f + ex2a(mA * zA1)) + dA;

        // gather all 4 gates within the 4-lane group: 3 bfly shuffles
        const float s10 = shflb(a0, 1);
        const float s11 = shflb(a1, 1);
        const float s20 = shflb(a0, 2);
        const float s21 = shflb(a1, 2);
        const float s30 = shflb(s10, 2);
        const float s31 = shflb(s11, 2);
        // (a,s1) = gates (2q, 2q+1); (s2,s3) = gates (2(1-q), 2(1-q)+1)
        const float lo0  = glo ? s10 : a0;
        const float hi0  = glo ? a0  : s10;
        const float olo0 = glo ? s30 : s20;
        const float ohi0 = glo ? s20 : s30;
        const float lo1  = glo ? s11 : a1;
        const float hi1  = glo ? a1  : s11;
        const float olo1 = glo ? s31 : s21;
        const float ohi1 = glo ? s21 : s31;
        const float gi0 = q ? olo0 : lo0;
        const float gf0 = q ? ohi0 : hi0;
        const float gg0 = q ? lo0  : olo0;
        const float go0 = q ? hi0  : ohi0;
        const float gi1 = q ? olo1 : lo1;
        const float gf1 = q ? ohi1 : hi1;
        const float gg1 = q ? lo1  : olo1;
        const float go1 = q ? hi1  : ohi1;

        c0 = gf0 * c0 + gi0 * gg0;
        c1 = gf1 * c1 + gi1 * gg1;
        const float h0v = go0 * tanha(c0);
        const float h1v = go1 * tanha(c1);

        if (g == 0) {
            hb[wbuf][bp * H_ + uu]       = h0v;
            hb[wbuf][(bp + 1) * H_ + uu] = h1v;
        }

        // flush xp_{t-2} from the read buffer (coalesced float4)
        if (t >= 2 && tid < 256) {
            const int fb  = tid >> 6;       // batch 0..3
            const int fq  = tid & 63;       // float4 index within row block
            const float4 v = reinterpret_cast<const float4*>(xps[rb] + fb * 256)[fq];
            reinterpret_cast<float4*>(
                xpo + ((size_t)(b0 + fb) * S_ + (t - 2)) * 256)[fq] = v;
        }

        if constexpr (L0) { x0 = nx0; x1 = nx1; }
        else { za0 = nza0; za1 = nza1; }

        __syncthreads();   // orders: hb/xps writes above vs next-iter reads
    }

    // epilogue 1: flush xp_{S-2} (staged during iter S-1)
    if (tid < 256) {
        const int fb = tid >> 6;
        const int fq = tid & 63;
        const float4 v = reinterpret_cast<const float4*>(xps[(S_ - 1) & 1] + fb * 256)[fq];
        reinterpret_cast<float4*>(
            xpo + ((size_t)(b0 + fb) * S_ + (S_ - 2)) * 256)[fq] = v;
    }
    // epilogue 2: compute + store xp_{S-1} directly from h_{S-1}
    {
        const UPair* v0 = reinterpret_cast<const UPair*>(hb[(S_ - 1) & 1] + bp * H_);
        const UPair* v1 = reinterpret_cast<const UPair*>(hb[(S_ - 1) & 1] + (bp + 1) * H_);
        ull X0 = 0ull, X1 = 0ull;
#pragma unroll
        for (int k = 0; k < 16; ++k) {
            const ull xl = wx[2 * k], xh = wx[2 * k + 1];
            const UPair a0 = v0[k];
            const UPair a1 = v1[k];
            X0 = ffma2(xl, a0.lo, X0); X0 = ffma2(xh, a0.hi, X0);
            X1 = ffma2(xl, a1.lo, X1); X1 = ffma2(xh, a1.hi, X1);
        }
        xpo[((size_t)(b0 + bp) * S_ + (S_ - 1)) * 256 + row]     = hadd2(X0) + bxr;
        xpo[((size_t)(b0 + bp + 1) * S_ + (S_ - 1)) * 256 + row] = hadd2(X1) + bxr;
    }
}

// ---------------------------------------------------------------------------
// Final-layer recurrent kernel (round-7 design, 256 threads, LAST_ONLY).
// Reads z[B][S][256] (bias folded), emits h_{S-1} only.
// ---------------------------------------------------------------------------
__global__ void __launch_bounds__(256, 1)
recur_last_kernel(const float* __restrict__ zin,
                  const float* __restrict__ Whh,
                  float* __restrict__ out)     // [B][64]
{
    __shared__ __align__(16) float hb[2][GB * H_];

    const int tid = threadIdx.x;
    const int w   = tid >> 5;
    const int l   = tid & 31;
    const int p   = l & 1;
    const int uu  = (w & 3) * 16 + (l >> 1);
    const int bp  = (w >> 2) * 2;
    const int b0  = blockIdx.x * GB;
    const int rowA = uu + p * 128;
    const int rowB = rowA + 64;

    ull wA[32], wB[32];
    {
        const ull* pa = reinterpret_cast<const ull*>(Whh + rowA * H_);
        const ull* pb = reinterpret_cast<const ull*>(Whh + rowB * H_);
#pragma unroll
        for (int k = 0; k < 32; ++k) { wA[k] = pa[k]; wB[k] = pb[k]; }
    }

    const float mA = p ? 2.8853900817779268f : -1.4426950408889634f;
    const float sA = p ? -2.0f : 1.0f;
    const float dA = p ? 1.0f : 0.0f;

    const float* zp0 = zin + (size_t)(b0 + bp) * S_ * 256 + rowA;
    const float* zp1 = zin + (size_t)(b0 + bp + 1) * S_ * 256 + rowA;
    float za0 = zp0[0], zb0 = zp0[64];
    float za1 = zp1[0], zb1 = zp1[64];

    float c0 = 0.0f, c1 = 0.0f;
    for (int i = tid; i < GB * H_; i += 256) hb[1][i] = 0.0f;
    __syncthreads();

    for (int t = 0; t < S_; ++t) {
        const UPair* v0 = reinterpret_cast<const UPair*>(hb[(t + 1) & 1] + bp * H_);
        const UPair* v1 = reinterpret_cast<const UPair*>(hb[(t + 1) & 1] + (bp + 1) * H_);

        float nza0 = 0, nzb0 = 0, nza1 = 0, nzb1 = 0;
        if (t + 1 < S_) {
            const size_t o = (size_t)(t + 1) * 256;
            nza0 = zp0[o]; nzb0 = zp0[o + 64];
            nza1 = zp1[o]; nzb1 = zp1[o + 64];
        }

        ull A0 = 0ull, B0 = 0ull, A1 = 0ull, B1 = 0ull;
#pragma unroll
        for (int k = 0; k < 16; ++k) {
            const ull wal = wA[2 * k], wah = wA[2 * k + 1];
            const ull wbl = wB[2 * k], wbh = wB[2 * k + 1];
            const UPair a0 = v0[k];
            const UPair a1 = v1[k];
            A0 = ffma2(wal, a0.lo, A0); A0 = ffma2(wah, a0.hi, A0);
            B0 = ffma2(wbl, a0.lo, B0); B0 = ffma2(wbh, a0.hi, B0);
            A1 = ffma2(wal, a1.lo, A1); A1 = ffma2(wah, a1.hi, A1);
            B1 = ffma2(wbl, a1.lo, B1); B1 = ffma2(wbh, a1.hi, B1);
        }
        const float zA0 = hadd2(A0) + za0;
        const float zB0 = hadd2(B0) + zb0;
        const float zA1 = hadd2(A1) + za1;
        const float zB1 = hadd2(B1) + zb1;

        const float aA0 = sA * rcpa(1.0f + ex2a(mA * zA0)) + dA;
        const float aA1 = sA * rcpa(1.0f + ex2a(mA * zA1)) + dA;
        const float aB0 = sigf(zB0);
        const float aB1 = sigf(zB1);

        const float oA0 = shflb(aA0, 1);
        const float oB0 = shflb(aB0, 1);
        const float oA1 = shflb(aA1, 1);
        const float oB1 = shflb(aB1, 1);
        const float gi0 = p ? oA0 : aA0;
        const float gf0 = p ? oB0 : aB0;
        const float gg0 = p ? aA0 : oA0;
        const float go0 = p ? aB0 : oB0;
        const float gi1 = p ? oA1 : aA1;
        const float gf1 = p ? oB1 : aB1;
        const float gg1 = p ? aA1 : oA1;
        const float go1 = p ? aB1 : oB1;

        c0 = gf0 * c0 + gi0 * gg0;
        c1 = gf1 * c1 + gi1 * gg1;
        const float h0v = go0 * tanha(c0);
        const float h1v = go1 * tanha(c1);

        if (p == 0) {
            hb[t & 1][bp * H_ + uu]       = h0v;
            hb[t & 1][(bp + 1) * H_ + uu] = h1v;
            if (t == S_ - 1) {
                out[(b0 + bp) * H_ + uu]     = h0v;
                out[(b0 + bp + 1) * H_ + uu] = h1v;
            }
        }

        za0 = nza0; zb0 = nzb0; za1 = nza1; zb1 = nzb1;
        __syncthreads();
    }
}

// out[b] = h_last[b] @ fc_w^T + fc_b
__global__ void fc_kernel(const float* __restrict__ hbuf,
                          const float* __restrict__ fw,
                          const float* __restrict__ fb,
                          float* __restrict__ outp)
{
    int b = blockIdx.x * blockDim.x + threadIdx.x;
    if (b >= B_) return;
    const float* h = hbuf + (size_t)b * H_;
    float a0 = fb[0], a1 = fb[1];
#pragma unroll
    for (int k = 0; k < H_; ++k) {
        float hv = h[k];
        a0 += hv * fw[k];
        a1 += hv * fw[H_ + k];
    }
    outp[b * 2 + 0] = a0;
    outp[b * 2 + 1] = a1;
}

extern "C" void kernel_launch(void* const* d_in, const int* in_sizes, int n_in,
                              void* d_out, int out_size)
{
    const float* x    = (const float*)d_in[0];
    const float* Wih0 = (const float*)d_in[1];
    const float* Whh0 = (const float*)d_in[2];
    const float* bih0 = (const float*)d_in[3];
    const float* bhh0 = (const float*)d_in[4];
    const float* Wih1 = (const float*)d_in[5];
    const float* Whh1 = (const float*)d_in[6];
    const float* bih1 = (const float*)d_in[7];
    const float* bhh1 = (const float*)d_in[8];
    const float* Wih2 = (const float*)d_in[9];
    const float* Whh2 = (const float*)d_in[10];
    const float* bih2 = (const float*)d_in[11];
    const float* bhh2 = (const float*)d_in[12];
    const float* fc_w = (const float*)d_in[13];
    const float* fc_b = (const float*)d_in[14];
    float* out = (float*)d_out;

    float *xp1, *xp2, *hlast;
    cudaGetSymbolAddress((void**)&xp1, g_xp1);
    cudaGetSymbolAddress((void**)&xp2, g_xp2);
    cudaGetSymbolAddress((void**)&hlast, g_hlast);

    // L0 recurrence + L1 projection fused
    fused_kernel<true><<<NCTA, 512>>>(x, Wih0, Whh0, bih0, bhh0,
                                      Wih1, bih1, bhh1, xp1);
    // L1 recurrence + L2 projection fused
    fused_kernel<false><<<NCTA, 512>>>(xp1, nullptr, Whh1, nullptr, nullptr,
                                       Wih2, bih2, bhh2, xp2);
    // L2 recurrence, last step only
    recur_last_kernel<<<NCTA, 256>>>(xp2, Whh2, hlast);
    // final linear
    fc_kernel<<<(B_ + 255) / 256, 256>>>(hlast, fc_w, fc_b, out);
}

// round 10
// speedup vs baseline: 1.9830x; 1.9830x over previous
#include <cuda_runtime.h>
#include <cstddef>

typedef unsigned long long ull;

#define B_   512
#define S_   2048
#define H_   64
#define GB   4                  // batch per CTA
#define NCTA (B_ / GB)          // 128 CTAs -> 1 per SM

// Scratch (sanctioned __device__ globals)
__device__ float g_xp1[(size_t)B_ * S_ * 256];
__device__ float g_xp2[(size_t)B_ * S_ * 256];
__device__ float g_hlast[B_ * H_];

struct alignas(16) UPair { ull lo, hi; };

__device__ __forceinline__ float ex2a(float x) {
    float y; asm("ex2.approx.ftz.f32 %0, %1;" : "=f"(y) : "f"(x)); return y;
}
__device__ __forceinline__ float rcpa(float x) {
    float y; asm("rcp.approx.ftz.f32 %0, %1;" : "=f"(y) : "f"(x)); return y;
}
__device__ __forceinline__ float sigf(float z) {
    return rcpa(1.0f + ex2a(-1.4426950408889634f * z));
}
__device__ __forceinline__ float tanha(float z) {
    return 1.0f - 2.0f * rcpa(1.0f + ex2a(2.8853900817779268f * z));
}
__device__ __forceinline__ ull ffma2(ull a, ull b, ull c) {
    ull d;
    asm("fma.rn.f32x2 %0, %1, %2, %3;" : "=l"(d) : "l"(a), "l"(b), "l"(c));
    return d;
}
__device__ __forceinline__ float hadd2(ull v) {
    float lo, hi;
    asm("mov.b64 {%0, %1}, %2;" : "=f"(lo), "=f"(hi) : "l"(v));
    return lo + hi;
}
__device__ __forceinline__ ull pack2(float lo, float hi) {
    ull d; asm("mov.b64 %0, {%1, %2};" : "=l"(d) : "f"(lo), "f"(hi)); return d;
}
__device__ __forceinline__ float shflb(float v, int x) {
    float r;
    asm("shfl.sync.bfly.b32 %0, %1, %2, 0x1F, 0xFFFFFFFF;"
        : "=r"(*(unsigned*)&r) : "r"(*(unsigned*)&v), "r"(x));
    return r;
}

// Dynamic smem layout (floats):
//   ws   [256 slots][68]   = 17408   (WihN, slot-major, stride-68 pad)
//   hb0  [256], hb1 [256]  (h ping-pong: [batch][uu])
//   xps0 [1024], xps1[1024] (xp staging ping-pong: [batch][row])
#define WS_FLOATS   (256 * 68)
#define SMEM_FLOATS (WS_FLOATS + 512 + 2048)

// ---------------------------------------------------------------------------
// Fused: layer recurrence + next-layer input projection.
// 512 threads. Thread = gate row (row = uu + 64g) x batches (bp, bp+1).
// Warps 0-7 (bp=0) ALSO compute xp row `row` for all 4 batches, with WihN
// read from smem (conflict-free: slot = uu*4+g = 32w+l, row stride 68 floats).
// One barrier per step. xps double-buffered, flushed with 2-step lag.
// ---------------------------------------------------------------------------
template <bool L0>
__global__ void __launch_bounds__(512, 1)
fused_kernel(const float* __restrict__ xin,   // L0: x[B][S][4]; else z[B][S][256]
             const float* __restrict__ Wih,   // L0 only [256][4]
             const float* __restrict__ Whh,   // [256][64]
             const float* __restrict__ bih,   // L0 only
             const float* __restrict__ bhh,   // L0 only
             const float* __restrict__ WihN,  // next layer [256][64]
             const float* __restrict__ bihN,
             const float* __restrict__ bhhN,
             float* __restrict__ xpo)         // next-layer z [B][S][256]
{
    extern __shared__ __align__(16) float sm[];
    float* ws   = sm;
    float* hb0  = sm + WS_FLOATS;
    float* hb1  = hb0 + 256;
    float* xps0 = hb1 + 256;
    float* xps1 = xps0 + 1024;

    const int tid = threadIdx.x;
    const int w   = tid >> 5;
    const int l   = tid & 31;
    const int g   = l & 3;                  // gate 0=i 1=f 2=g 3=o
    const int q   = g >> 1;
    const int glo = g & 1;
    const int uu  = (w & 7) * 8 + (l >> 2);
    const int bp  = (w >> 3) * 2;           // 0 (warps 0-7) or 2
    const int b0  = blockIdx.x * GB;
    const int row = uu + g * 64;
    const bool isxp = (w < 8);

    // populate ws: WihN[row][k] -> slot (uu*4+g), stride 68
    for (int i = tid; i < 256 * 64; i += 512) {
        const int r = i >> 6, k = i & 63;
        const int slot = (r & 63) * 4 + (r >> 6);
        ws[slot * 68 + k] = WihN[i];
    }
    if (tid < 256) hb1[tid] = 0.0f;   // h_{-1} = 0 (t=0 reads hb1)

    // gate-row recurrent weights in registers
    ull wg[32];
    {
        const ull* pg = reinterpret_cast<const ull*>(Whh + row * H_);
#pragma unroll
        for (int k = 0; k < 32; ++k) wg[k] = pg[k];
    }
    const float bxr = bihN[row] + bhhN[row];
    const float* wsrow = ws + (uu * 4 + g) * 68;   // own xp row in smem

    // gate activation params: g==2 tanh else sigmoid (uniform stream)
    const float mA = (g == 2) ? 2.8853900817779268f : -1.4426950408889634f;
    const float sA = (g == 2) ? -2.0f : 1.0f;
    const float dA = (g == 2) ? 1.0f : 0.0f;

    float biasr = 0.0f;
    ull wi0 = 0, wi1 = 0;
    const float4 *xq0 = nullptr, *xq1 = nullptr;
    const float  *zq0 = nullptr, *zq1 = nullptr;
    float4 x0, x1; float za0 = 0.0f, za1 = 0.0f;

    if constexpr (L0) {
        biasr = bih[row] + bhh[row];
        const ull* wi = reinterpret_cast<const ull*>(Wih + row * 4);
        wi0 = wi[0]; wi1 = wi[1];
        xq0 = reinterpret_cast<const float4*>(xin + (size_t)(b0 + bp) * S_ * 4);
        xq1 = reinterpret_cast<const float4*>(xin + (size_t)(b0 + bp + 1) * S_ * 4);
        x0 = xq0[0]; x1 = xq1[0];
    } else {
        zq0 = xin + (size_t)(b0 + bp) * S_ * 256 + row;
        zq1 = xin + (size_t)(b0 + bp + 1) * S_ * 256 + row;
        za0 = zq0[0]; za1 = zq1[0];
    }

    float c0 = 0.0f, c1 = 0.0f;
    __syncthreads();   // ws + hb1 init visible

    for (int t = 0; t < S_; ++t) {
        const float* hr = (t & 1) ? hb0 : hb1;   // h_{t-1}
        float*       hw = (t & 1) ? hb1 : hb0;   // h_t
        float*       xw = (t & 1) ? xps1 : xps0; // stage xp_{t-1}
        const float* xr = (t & 1) ? xps0 : xps1; // flush xp_{t-2}

        // prefetch next step's input
        float4 nx0, nx1; float nza0 = 0.0f, nza1 = 0.0f;
        if (t + 1 < S_) {
            if constexpr (L0) { nx0 = xq0[t + 1]; nx1 = xq1[t + 1]; }
            else {
                const size_t o = (size_t)(t + 1) * 256;
                nza0 = zq0[o]; nza1 = zq1[o];
            }
        }

        ull A0 = 0ull, A1 = 0ull;
        if (isxp) {
            // gates (batches 0,1) + xp (batches 0-3); shares h loads
            const UPair* v0 = reinterpret_cast<const UPair*>(hr);
            const UPair* v1 = reinterpret_cast<const UPair*>(hr + 64);
            const UPair* v2 = reinterpret_cast<const UPair*>(hr + 128);
            const UPair* v3 = reinterpret_cast<const UPair*>(hr + 192);
            const UPair* wxp = reinterpret_cast<const UPair*>(wsrow);
            ull X0 = 0ull, X1 = 0ull, X2 = 0ull, X3 = 0ull;
#pragma unroll
            for (int k = 0; k < 16; ++k) {
                const ull gl = wg[2 * k], gh = wg[2 * k + 1];
                const UPair wx = wxp[k];
                const UPair a0 = v0[k];
                const UPair a1 = v1[k];
                const UPair a2 = v2[k];
                const UPair a3 = v3[k];
                A0 = ffma2(gl, a0.lo, A0); A0 = ffma2(gh, a0.hi, A0);
                A1 = ffma2(gl, a1.lo, A1); A1 = ffma2(gh, a1.hi, A1);
                X0 = ffma2(wx.lo, a0.lo, X0); X0 = ffma2(wx.hi, a0.hi, X0);
                X1 = ffma2(wx.lo, a1.lo, X1); X1 = ffma2(wx.hi, a1.hi, X1);
                X2 = ffma2(wx.lo, a2.lo, X2); X2 = ffma2(wx.hi, a2.hi, X2);
                X3 = ffma2(wx.lo, a3.lo, X3); X3 = ffma2(wx.hi, a3.hi, X3);
            }
            // stage xp_{t-1} (garbage at t==0; never read)
            xw[row]       = hadd2(X0) + bxr;
            xw[256 + row] = hadd2(X1) + bxr;
            xw[512 + row] = hadd2(X2) + bxr;
            xw[768 + row] = hadd2(X3) + bxr;
        } else {
            // gates only (batches 2,3)
            const UPair* v0 = reinterpret_cast<const UPair*>(hr + bp * 64);
            const UPair* v1 = reinterpret_cast<const UPair*>(hr + (bp + 1) * 64);
#pragma unroll
            for (int k = 0; k < 16; ++k) {
                const ull gl = wg[2 * k], gh = wg[2 * k + 1];
                const UPair a0 = v0[k];
                const UPair a1 = v1[k];
                A0 = ffma2(gl, a0.lo, A0); A0 = ffma2(gh, a0.hi, A0);
                A1 = ffma2(gl, a1.lo, A1); A1 = ffma2(gh, a1.hi, A1);
            }
        }

        float zA0, zA1;
        if constexpr (L0) {
            A0 = ffma2(wi0, pack2(x0.x, x0.y), A0); A0 = ffma2(wi1, pack2(x0.z, x0.w), A0);
            A1 = ffma2(wi0, pack2(x1.x, x1.y), A1); A1 = ffma2(wi1, pack2(x1.z, x1.w), A1);
            zA0 = hadd2(A0) + biasr;
            zA1 = hadd2(A1) + biasr;
        } else {
            zA0 = hadd2(A0) + za0;
            zA1 = hadd2(A1) + za1;
        }

        const float a0 = sA * rcpa(1.0f + ex2a(mA * zA0)) + dA;
        const float a1 = sA * rcpa(1.0f + ex2a(mA * zA1)) + dA;

        // gather 4 gates within 4-lane group (3 bfly shuffles)
        const float s10 = shflb(a0, 1);
        const float s11 = shflb(a1, 1);
        const float s20 = shflb(a0, 2);
        const float s21 = shflb(a1, 2);
        const float s30 = shflb(s10, 2);
        const float s31 = shflb(s11, 2);
        const float lo0  = glo ? s10 : a0;
        const float hi0  = glo ? a0  : s10;
        const float olo0 = glo ? s30 : s20;
        const float ohi0 = glo ? s20 : s30;
        const float lo1  = glo ? s11 : a1;
        const float hi1  = glo ? a1  : s11;
        const float olo1 = glo ? s31 : s21;
        const float ohi1 = glo ? s21 : s31;
        const float gi0 = q ? olo0 : lo0;
        const float gf0 = q ? ohi0 : hi0;
        const float gg0 = q ? lo0  : olo0;
        const float go0 = q ? hi0  : ohi0;
        const float gi1 = q ? olo1 : lo1;
        const float gf1 = q ? ohi1 : hi1;
        const float gg1 = q ? lo1  : olo1;
        const float go1 = q ? hi1  : ohi1;

        c0 = gf0 * c0 + gi0 * gg0;
        c1 = gf1 * c1 + gi1 * gg1;
        const float h0v = go0 * tanha(c0);
        const float h1v = go1 * tanha(c1);

        if (g == 0) {
            hw[bp * 64 + uu]       = h0v;
            hw[(bp + 1) * 64 + uu] = h1v;
        }

        // flush xp_{t-2} (coalesced float4)
        if (t >= 2 && tid < 256) {
            const int fb = tid >> 6;
            const int fq = tid & 63;
            const float4 v = reinterpret_cast<const float4*>(xr + fb * 256)[fq];
            reinterpret_cast<float4*>(
                xpo + ((size_t)(b0 + fb) * S_ + (t - 2)) * 256)[fq] = v;
        }

        if constexpr (L0) { x0 = nx0; x1 = nx1; }
        else { za0 = nza0; za1 = nza1; }

        __syncthreads();   // orders hw/xw writes vs next-iter reads
    }

    // epilogue 1: flush xp_{S-2} (staged during iter S-1)
    {
        const float* xl = ((S_ - 1) & 1) ? xps1 : xps0;
        if (tid < 256) {
            const int fb = tid >> 6;
            const int fq = tid & 63;
            const float4 v = reinterpret_cast<const float4*>(xl + fb * 256)[fq];
            reinterpret_cast<float4*>(
                xpo + ((size_t)(b0 + fb) * S_ + (S_ - 2)) * 256)[fq] = v;
        }
    }
    // epilogue 2: compute + store xp_{S-1} from h_{S-1}
    if (isxp) {
        const float* hr = ((S_ - 1) & 1) ? hb1 : hb0;
        const UPair* v0 = reinterpret_cast<const UPair*>(hr);
        const UPair* v1 = reinterpret_cast<const UPair*>(hr + 64);
        const UPair* v2 = reinterpret_cast<const UPair*>(hr + 128);
        const UPair* v3 = reinterpret_cast<const UPair*>(hr + 192);
        const UPair* wxp = reinterpret_cast<const UPair*>(wsrow);
        ull X0 = 0ull, X1 = 0ull, X2 = 0ull, X3 = 0ull;
#pragma unroll
        for (int k = 0; k < 16; ++k) {
            const UPair wx = wxp[k];
            const UPair a0 = v0[k];
            const UPair a1 = v1[k];
            const UPair a2 = v2[k];
            const UPair a3 = v3[k];
            X0 = ffma2(wx.lo, a0.lo, X0); X0 = ffma2(wx.hi, a0.hi, X0);
            X1 = ffma2(wx.lo, a1.lo, X1); X1 = ffma2(wx.hi, a1.hi, X1);
            X2 = ffma2(wx.lo, a2.lo, X2); X2 = ffma2(wx.hi, a2.hi, X2);
            X3 = ffma2(wx.lo, a3.lo, X3); X3 = ffma2(wx.hi, a3.hi, X3);
        }
        xpo[((size_t)(b0 + 0) * S_ + (S_ - 1)) * 256 + row] = hadd2(X0) + bxr;
        xpo[((size_t)(b0 + 1) * S_ + (S_ - 1)) * 256 + row] = hadd2(X1) + bxr;
        xpo[((size_t)(b0 + 2) * S_ + (S_ - 1)) * 256 + row] = hadd2(X2) + bxr;
        xpo[((size_t)(b0 + 3) * S_ + (S_ - 1)) * 256 + row] = hadd2(X3) + bxr;
    }
}

// ---------------------------------------------------------------------------
// Final-layer recurrence (R7 design, 256 threads, last step only).
// ---------------------------------------------------------------------------
__global__ void __launch_bounds__(256, 1)
recur_last_kernel(const float* __restrict__ zin,
                  const float* __restrict__ Whh,
                  float* __restrict__ out)     // [B][64]
{
    __shared__ __align__(16) float hb[2][GB * H_];

    const int tid = threadIdx.x;
    const int w   = tid >> 5;
    const int l   = tid & 31;
    const int p   = l & 1;
    const int uu  = (w & 3) * 16 + (l >> 1);
    const int bp  = (w >> 2) * 2;
    const int b0  = blockIdx.x * GB;
    const int rowA = uu + p * 128;
    const int rowB = rowA + 64;

    ull wA[32], wB[32];
    {
        const ull* pa = reinterpret_cast<const ull*>(Whh + rowA * H_);
        const ull* pb = reinterpret_cast<const ull*>(Whh + rowB * H_);
#pragma unroll
        for (int k = 0; k < 32; ++k) { wA[k] = pa[k]; wB[k] = pb[k]; }
    }

    const float mA = p ? 2.8853900817779268f : -1.4426950408889634f;
    const float sA = p ? -2.0f : 1.0f;
    const float dA = p ? 1.0f : 0.0f;

    const float* zp0 = zin + (size_t)(b0 + bp) * S_ * 256 + rowA;
    const float* zp1 = zin + (size_t)(b0 + bp + 1) * S_ * 256 + rowA;
    float za0 = zp0[0], zb0 = zp0[64];
    float za1 = zp1[0], zb1 = zp1[64];

    float c0 = 0.0f, c1 = 0.0f;
    for (int i = tid; i < GB * H_; i += 256) hb[1][i] = 0.0f;
    __syncthreads();

    for (int t = 0; t < S_; ++t) {
        const UPair* v0 = reinterpret_cast<const UPair*>(hb[(t + 1) & 1] + bp * H_);
        const UPair* v1 = reinterpret_cast<const UPair*>(hb[(t + 1) & 1] + (bp + 1) * H_);

        float nza0 = 0, nzb0 = 0, nza1 = 0, nzb1 = 0;
        if (t + 1 < S_) {
            const size_t o = (size_t)(t + 1) * 256;
            nza0 = zp0[o]; nzb0 = zp0[o + 64];
            nza1 = zp1[o]; nzb1 = zp1[o + 64];
        }

        ull A0 = 0ull, B0 = 0ull, A1 = 0ull, B1 = 0ull;
#pragma unroll
        for (int k = 0; k < 16; ++k) {
            const ull wal = wA[2 * k], wah = wA[2 * k + 1];
            const ull wbl = wB[2 * k], wbh = wB[2 * k + 1];
            const UPair a0 = v0[k];
            const UPair a1 = v1[k];
            A0 = ffma2(wal, a0.lo, A0); A0 = ffma2(wah, a0.hi, A0);
            B0 = ffma2(wbl, a0.lo, B0); B0 = ffma2(wbh, a0.hi, B0);
            A1 = ffma2(wal, a1.lo, A1); A1 = ffma2(wah, a1.hi, A1);
            B1 = ffma2(wbl, a1.lo, B1); B1 = ffma2(wbh, a1.hi, B1);
        }
        const float zA0 = hadd2(A0) + za0;
        const float zB0 = hadd2(B0) + zb0;
        const float zA1 = hadd2(A1) + za1;
        const float zB1 = hadd2(B1) + zb1;

        const float aA0 = sA * rcpa(1.0f + ex2a(mA * zA0)) + dA;
        const float aA1 = sA * rcpa(1.0f + ex2a(mA * zA1)) + dA;
        const float aB0 = sigf(zB0);
        const float aB1 = sigf(zB1);

        const float oA0 = shflb(aA0, 1);
        const float oB0 = shflb(aB0, 1);
        const float oA1 = shflb(aA1, 1);
        const float oB1 = shflb(aB1, 1);
        const float gi0 = p ? oA0 : aA0;
        const float gf0 = p ? oB0 : aB0;
        const float gg0 = p ? aA0 : oA0;
        const float go0 = p ? aB0 : oB0;
        const float gi1 = p ? oA1 : aA1;
        const float gf1 = p ? oB1 : aB1;
        const float gg1 = p ? aA1 : oA1;
        const float go1 = p ? aB1 : oB1;

        c0 = gf0 * c0 + gi0 * gg0;
        c1 = gf1 * c1 + gi1 * gg1;
        const float h0v = go0 * tanha(c0);
        const float h1v = go1 * tanha(c1);

        if (p == 0) {
            hb[t & 1][bp * H_ + uu]       = h0v;
            hb[t & 1][(bp + 1) * H_ + uu] = h1v;
            if (t == S_ - 1) {
                out[(b0 + bp) * H_ + uu]     = h0v;
                out[(b0 + bp + 1) * H_ + uu] = h1v;
            }
        }

        za0 = nza0; zb0 = nzb0; za1 = nza1; zb1 = nzb1;
        __syncthreads();
    }
}

// out[b] = h_last[b] @ fc_w^T + fc_b
__global__ void fc_kernel(const float* __restrict__ hbuf,
                          const float* __restrict__ fw,
                          const float* __restrict__ fb,
                          float* __restrict__ outp)
{
    int b = blockIdx.x * blockDim.x + threadIdx.x;
    if (b >= B_) return;
    const float* h = hbuf + (size_t)b * H_;
    float a0 = fb[0], a1 = fb[1];
#pragma unroll
    for (int k = 0; k < H_; ++k) {
        float hv = h[k];
        a0 += hv * fw[k];
        a1 += hv * fw[H_ + k];
    }
    outp[b * 2 + 0] = a0;
    outp[b * 2 + 1] = a1;
}

extern "C" void kernel_launch(void* const* d_in, const int* in_sizes, int n_in,
                              void* d_out, int out_size)
{
    const float* x    = (const float*)d_in[0];
    const float* Wih0 = (const float*)d_in[1];
    const float* Whh0 = (const float*)d_in[2];
    const float* bih0 = (const float*)d_in[3];
    const float* bhh0 = (const float*)d_in[4];
    const float* Wih1 = (const float*)d_in[5];
    const float* Whh1 = (const float*)d_in[6];
    const float* bih1 = (const float*)d_in[7];
    const float* bhh1 = (const float*)d_in[8];
    const float* Wih2 = (const float*)d_in[9];
    const float* Whh2 = (const float*)d_in[10];
    const float* bih2 = (const float*)d_in[11];
    const float* bhh2 = (const float*)d_in[12];
    const float* fc_w = (const float*)d_in[13];
    const float* fc_b = (const float*)d_in[14];
    float* out = (float*)d_out;

    float *xp1, *xp2, *hlast;
    cudaGetSymbolAddress((void**)&xp1, g_xp1);
    cudaGetSymbolAddress((void**)&xp2, g_xp2);
    cudaGetSymbolAddress((void**)&hlast, g_hlast);

    const int FSMEM = SMEM_FLOATS * sizeof(float);   // ~80 KB

    cudaFuncSetAttribute(fused_kernel<true>,
                         cudaFuncAttributeMaxDynamicSharedMemorySize, FSMEM);
    cudaFuncSetAttribute(fused_kernel<false>,
                         cudaFuncAttributeMaxDynamicSharedMemorySize, FSMEM);

    fused_kernel<true><<<NCTA, 512, FSMEM>>>(x, Wih0, Whh0, bih0, bhh0,
                                             Wih1, bih1, bhh1, xp1);
    fused_kernel<false><<<NCTA, 512, FSMEM>>>(xp1, nullptr, Whh1, nullptr, nullptr,
                                              Wih2, bih2, bhh2, xp2);
    recur_last_kernel<<<NCTA, 256>>>(xp2, Whh2, hlast);
    fc_kernel<<<(B_ + 255) / 256, 256>>>(hlast, fc_w, fc_b, out);
}

// round 11
// speedup vs baseline: 2.1978x; 1.1083x over previous
#include <cuda_runtime.h>
#include <cstddef>

typedef unsigned long long ull;

#define B_   512
#define S_   2048
#define H_   64
#define GB   4                  // batch per recurrent CTA
#define NCTA (B_ / GB)          // 128 CTAs -> 1 per SM
#define PST  64                 // proj s-tile

// Scratch (sanctioned __device__ globals)
__device__ float g_h0[(size_t)B_ * S_ * H_];
__device__ float g_h1[(size_t)B_ * S_ * H_];
__device__ float g_xp[(size_t)B_ * S_ * 4 * H_];
__device__ float g_hlast[B_ * H_];
__device__ float g_wt[64 * 256];     // transposed proj weights [k][r]
__device__ float g_bs[256];          // bih + bhh

struct alignas(16) UPair { ull lo, hi; };

__device__ __forceinline__ float ex2a(float x) {
    float y; asm("ex2.approx.ftz.f32 %0, %1;" : "=f"(y) : "f"(x)); return y;
}
__device__ __forceinline__ float rcpa(float x) {
    float y; asm("rcp.approx.ftz.f32 %0, %1;" : "=f"(y) : "f"(x)); return y;
}
__device__ __forceinline__ float sigf(float z) {
    return rcpa(1.0f + ex2a(-1.4426950408889634f * z));
}
__device__ __forceinline__ float tanha(float z) {
    return 1.0f - 2.0f * rcpa(1.0f + ex2a(2.8853900817779268f * z));
}
__device__ __forceinline__ ull ffma2(ull a, ull b, ull c) {
    ull d;
    asm("fma.rn.f32x2 %0, %1, %2, %3;" : "=l"(d) : "l"(a), "l"(b), "l"(c));
    return d;
}
__device__ __forceinline__ float hadd2(ull v) {
    float lo, hi;
    asm("mov.b64 {%0, %1}, %2;" : "=f"(lo), "=f"(hi) : "l"(v));
    return lo + hi;
}
__device__ __forceinline__ ull pack2(float lo, float hi) {
    ull d; asm("mov.b64 %0, {%1, %2};" : "=l"(d) : "f"(lo), "f"(hi)); return d;
}
__device__ __forceinline__ void unpack2(ull v, float& lo, float& hi) {
    asm("mov.b64 {%0, %1}, %2;" : "=f"(lo), "=f"(hi) : "l"(v));
}
__device__ __forceinline__ float shflb(float v, int x) {
    float r;
    asm("shfl.sync.bfly.b32 %0, %1, %2, 0x1F, 0xFFFFFFFF;"
        : "=r"(*(unsigned*)&r) : "r"(*(unsigned*)&v), "r"(x));
    return r;
}

// ---------------------------------------------------------------------------
// Weight transpose + bias fold (one-time per layer, tiny).
// ---------------------------------------------------------------------------
__global__ void wt_kernel(const float* __restrict__ W,
                          const float* __restrict__ bih,
                          const float* __restrict__ bhh,
                          float* __restrict__ Wt,
                          float* __restrict__ bs)
{
    const int r = threadIdx.x;
    const int k = blockIdx.x;
    Wt[k * 256 + r] = W[r * 64 + k];
    if (k == 0) bs[r] = bih[r] + bhh[r];
}

// ---------------------------------------------------------------------------
// Outer-product proj GEMM (round-7 design, unchanged — measured good).
// ---------------------------------------------------------------------------
__global__ void __launch_bounds__(256, 2)
proj_kernel(const float* __restrict__ in,
            const float* __restrict__ Wt,
            const float* __restrict__ bs,
            float* __restrict__ out)
{
    extern __shared__ float sm[];
    float* xT = sm;                 // [64][68]
    float* ws = sm + 64 * 68;       // [64][256]

    const int tid = threadIdx.x;
    const int rg  = tid & 15;
    const int sg  = tid >> 4;
    const int stile = blockIdx.x & (S_ / PST - 1);
    const int b     = blockIdx.x / (S_ / PST);
    const size_t base = (size_t)b * S_ + (size_t)stile * PST;

    {
        const float4* gw = reinterpret_cast<const float4*>(Wt);
        float4* sw = reinterpret_cast<float4*>(ws);
        for (int i = tid; i < 64 * 256 / 4; i += 256) sw[i] = gw[i];
    }
    {
        const int sL = tid & 63;
        const int kq = tid >> 6;
        const float4* gin = reinterpret_cast<const float4*>(in + (base + sL) * H_);
#pragma unroll
        for (int it = 0; it < 4; ++it) {
            const int k4 = kq * 4 + it;
            const float4 v = gin[k4];
            xT[(4 * k4 + 0) * 68 + sL] = v.x;
            xT[(4 * k4 + 1) * 68 + sL] = v.y;
            xT[(4 * k4 + 2) * 68 + sL] = v.z;
            xT[(4 * k4 + 3) * 68 + sL] = v.w;
        }
    }
    __syncthreads();

    const UPair*  wsp = reinterpret_cast<const UPair*>(ws);
    const float4* xT4 = reinterpret_cast<const float4*>(xT);

    ull acc[4][4][2];
#pragma unroll
    for (int s = 0; s < 4; ++s)
#pragma unroll
        for (int j = 0; j < 4; ++j) { acc[s][j][0] = 0ull; acc[s][j][1] = 0ull; }

#pragma unroll 4
    for (int k = 0; k < 64; ++k) {
        const UPair w0 = wsp[k * 64 + rg];
        const UPair w1 = wsp[k * 64 + 16 + rg];
        const UPair w2 = wsp[k * 64 + 32 + rg];
        const UPair w3 = wsp[k * 64 + 48 + rg];
        const float4 av = xT4[k * 17 + sg];
        ull ar[4] = {pack2(av.x, av.x), pack2(av.y, av.y),
                     pack2(av.z, av.z), pack2(av.w, av.w)};
#pragma unroll
        for (int s = 0; s < 4; ++s) {
            acc[s][0][0] = ffma2(w0.lo, ar[s], acc[s][0][0]);
            acc[s][0][1] = ffma2(w0.hi, ar[s], acc[s][0][1]);
            acc[s][1][0] = ffma2(w1.lo, ar[s], acc[s][1][0]);
            acc[s][1][1] = ffma2(w1.hi, ar[s], acc[s][1][1]);
            acc[s][2][0] = ffma2(w2.lo, ar[s], acc[s][2][0]);
            acc[s][2][1] = ffma2(w2.hi, ar[s], acc[s][2][1]);
            acc[s][3][0] = ffma2(w3.lo, ar[s], acc[s][3][0]);
            acc[s][3][1] = ffma2(w3.hi, ar[s], acc[s][3][1]);
        }
    }

    float4 bv[4];
#pragma unroll
    for (int j = 0; j < 4; ++j)
        bv[j] = reinterpret_cast<const float4*>(bs)[16 * j + rg];
#pragma unroll
    for (int s = 0; s < 4; ++s) {
        const size_t srow = base + 4 * sg + s;
        float4* op = reinterpret_cast<float4*>(out + srow * 256);
#pragma unroll
        for (int j = 0; j < 4; ++j) {
            float x0, x1, x2, x3;
            unpack2(acc[s][j][0], x0, x1);
            unpack2(acc[s][j][1], x2, x3);
            float4 o;
            o.x = x0 + bv[j].x; o.y = x1 + bv[j].y;
            o.z = x2 + bv[j].z; o.w = x3 + bv[j].w;
            op[16 * j + rg] = o;
        }
    }
}

// ---------------------------------------------------------------------------
// Recurrent kernel: 512 threads, 16 warps, ONE barrier per step.
// Thread = gate row (row = uu + 64g) x batches (bp, bp+1).
// Lane map: g = l&3 (gate 0..3), uu = (w&7)*8 + (l>>2), bp = (w>>3)*2.
// 4 lanes of a gate group gather all 4 gates via 3 bfly shuffles; c/h are
// computed redundantly in the group; g==0 lane publishes h (and out).
// Validated mapping (R9/R10 passed correctness); no fused xp work.
// ---------------------------------------------------------------------------
template <bool L0, bool LAST_ONLY>
__global__ void __launch_bounds__(512, 1)
recur_kernel(const float* __restrict__ xin,   // L0: x[B][S][4]; else z[B][S][256]
             const float* __restrict__ Wih,   // L0 only [256][4]
             const float* __restrict__ Whh,   // [256][64]
             const float* __restrict__ bih,   // L0 only
             const float* __restrict__ bhh,   // L0 only
             float* __restrict__ out)         // [B][S][64] or [B][64]
{
    __shared__ __align__(16) float hb[2][GB * H_];   // h ping-pong

    const int tid = threadIdx.x;
    const int w   = tid >> 5;
    const int l   = tid & 31;
    const int g   = l & 3;                  // gate 0=i 1=f 2=g 3=o
    const int q   = g >> 1;
    const int glo = g & 1;
    const int uu  = (w & 7) * 8 + (l >> 2); // 0..63
    const int bp  = (w >> 3) * 2;           // 0 or 2
    const int b0  = blockIdx.x * GB;
    const int row = uu + g * 64;

    // gate-row recurrent weights in registers (64 regs)
    ull wg[32];
    {
        const ull* pg = reinterpret_cast<const ull*>(Whh + row * H_);
#pragma unroll
        for (int k = 0; k < 32; ++k) wg[k] = pg[k];
    }

    // activation params: g==2 tanh else sigmoid (uniform instruction stream)
    const float mA = (g == 2) ? 2.8853900817779268f : -1.4426950408889634f;
    const float sA = (g == 2) ? -2.0f : 1.0f;
    const float dA = (g == 2) ? 1.0f : 0.0f;

    float biasr = 0.0f;
    ull wi0 = 0, wi1 = 0;
    const float4 *xq0 = nullptr, *xq1 = nullptr;
    const float  *zq0 = nullptr, *zq1 = nullptr;
    float4 x0, x1; float za0 = 0.0f, za1 = 0.0f;

    if constexpr (L0) {
        biasr = bih[row] + bhh[row];
        const ull* wi = reinterpret_cast<const ull*>(Wih + row * 4);
        wi0 = wi[0]; wi1 = wi[1];
        xq0 = reinterpret_cast<const float4*>(xin + (size_t)(b0 + bp) * S_ * 4);
        xq1 = reinterpret_cast<const float4*>(xin + (size_t)(b0 + bp + 1) * S_ * 4);
        x0 = xq0[0]; x1 = xq1[0];
    } else {
        zq0 = xin + (size_t)(b0 + bp) * S_ * 256 + row;
        zq1 = xin + (size_t)(b0 + bp + 1) * S_ * 256 + row;
        za0 = zq0[0]; za1 = zq1[0];
    }

    float c0 = 0.0f, c1 = 0.0f;
    for (int i = tid; i < GB * H_; i += 512) hb[1][i] = 0.0f;   // h_{-1}=0
    __syncthreads();

    for (int t = 0; t < S_; ++t) {
        const float* hr = hb[(t + 1) & 1];   // h_{t-1}
        float*       hw = hb[t & 1];         // h_t
        const UPair* v0 = reinterpret_cast<const UPair*>(hr + bp * H_);
        const UPair* v1 = reinterpret_cast<const UPair*>(hr + (bp + 1) * H_);

        // prefetch next step's input (hidden under the FMA loop)
        float4 nx0, nx1; float nza0 = 0.0f, nza1 = 0.0f;
        if (t + 1 < S_) {
            if constexpr (L0) { nx0 = xq0[t + 1]; nx1 = xq1[t + 1]; }
            else {
                const size_t o = (size_t)(t + 1) * 256;
                nza0 = zq0[o]; nza1 = zq1[o];
            }
        }

        // 2 dots (1 gate row x 2 batches)
        ull A0 = 0ull, A1 = 0ull;
#pragma unroll
        for (int k = 0; k < 16; ++k) {
            const ull gl = wg[2 * k], gh = wg[2 * k + 1];
            const UPair a0 = v0[k];
            const UPair a1 = v1[k];
            A0 = ffma2(gl, a0.lo, A0); A0 = ffma2(gh, a0.hi, A0);
            A1 = ffma2(gl, a1.lo, A1); A1 = ffma2(gh, a1.hi, A1);
        }

        float zA0, zA1;
        if constexpr (L0) {
            A0 = ffma2(wi0, pack2(x0.x, x0.y), A0); A0 = ffma2(wi1, pack2(x0.z, x0.w), A0);
            A1 = ffma2(wi0, pack2(x1.x, x1.y), A1); A1 = ffma2(wi1, pack2(x1.z, x1.w), A1);
            zA0 = hadd2(A0) + biasr;
            zA1 = hadd2(A1) + biasr;
        } else {
            zA0 = hadd2(A0) + za0;
            zA1 = hadd2(A1) + za1;
        }

        // activation (param-unified sigmoid/tanh)
        const float a0 = sA * rcpa(1.0f + ex2a(mA * zA0)) + dA;
        const float a1 = sA * rcpa(1.0f + ex2a(mA * zA1)) + dA;

        // gather 4 gates within the 4-lane group: 3 bfly shuffles
        const float s10 = shflb(a0, 1);
        const float s11 = shflb(a1, 1);
        const float s20 = shflb(a0, 2);
        const float s21 = shflb(a1, 2);
        const float s30 = shflb(s10, 2);
        const float s31 = shflb(s11, 2);
        const float lo0  = glo ? s10 : a0;
        const float hi0  = glo ? a0  : s10;
        const float olo0 = glo ? s30 : s20;
        const float ohi0 = glo ? s20 : s30;
        const float lo1  = glo ? s11 : a1;
        const float hi1  = glo ? a1  : s11;
        const float olo1 = glo ? s31 : s21;
        const float ohi1 = glo ? s21 : s31;
        const float gi0 = q ? olo0 : lo0;
        const float gf0 = q ? ohi0 : hi0;
        const float gg0 = q ? lo0  : olo0;
        const float go0 = q ? hi0  : ohi0;
        const float gi1 = q ? olo1 : lo1;
        const float gf1 = q ? ohi1 : hi1;
        const float gg1 = q ? lo1  : olo1;
        const float go1 = q ? hi1  : ohi1;

        c0 = gf0 * c0 + gi0 * gg0;
        c1 = gf1 * c1 + gi1 * gg1;
        const float h0v = go0 * tanha(c0);
        const float h1v = go1 * tanha(c1);

        if (g == 0) {
            hw[bp * H_ + uu]       = h0v;
            hw[(bp + 1) * H_ + uu] = h1v;
            if constexpr (LAST_ONLY) {
                if (t == S_ - 1) {
                    out[(b0 + bp) * H_ + uu]     = h0v;
                    out[(b0 + bp + 1) * H_ + uu] = h1v;
                }
            } else {
                out[((size_t)(b0 + bp) * S_ + t) * H_ + uu]     = h0v;
                out[((size_t)(b0 + bp + 1) * S_ + t) * H_ + uu] = h1v;
            }
        }

        if constexpr (L0) { x0 = nx0; x1 = nx1; }
        else { za0 = nza0; za1 = nza1; }

        __syncthreads();   // h_t published before next step's reads
    }
}

// out[b] = h_last[b] @ fc_w^T + fc_b
__global__ void fc_kernel(const float* __restrict__ hbuf,
                          const float* __restrict__ fw,
                          const float* __restrict__ fb,
                          float* __restrict__ outp)
{
    int b = blockIdx.x * blockDim.x + threadIdx.x;
    if (b >= B_) return;
    const float* h = hbuf + (size_t)b * H_;
    float a0 = fb[0], a1 = fb[1];
#pragma unroll
    for (int k = 0; k < H_; ++k) {
        float hv = h[k];
        a0 += hv * fw[k];
        a1 += hv * fw[H_ + k];
    }
    outp[b * 2 + 0] = a0;
    outp[b * 2 + 1] = a1;
}

extern "C" void kernel_launch(void* const* d_in, const int* in_sizes, int n_in,
                              void* d_out, int out_size)
{
    const float* x    = (const float*)d_in[0];
    const float* Wih0 = (const float*)d_in[1];
    const float* Whh0 = (const float*)d_in[2];
    const float* bih0 = (const float*)d_in[3];
    const float* bhh0 = (const float*)d_in[4];
    const float* Wih1 = (const float*)d_in[5];
    const float* Whh1 = (const float*)d_in[6];
    const float* bih1 = (const float*)d_in[7];
    const float* bhh1 = (const float*)d_in[8];
    const float* Wih2 = (const float*)d_in[9];
    const float* Whh2 = (const float*)d_in[10];
    const float* bih2 = (const float*)d_in[11];
    const float* bhh2 = (const float*)d_in[12];
    const float* fc_w = (const float*)d_in[13];
    const float* fc_b = (const float*)d_in[14];
    float* out = (float*)d_out;

    float *h0, *h1, *xp, *hlast, *wt, *bsv;
    cudaGetSymbolAddress((void**)&h0, g_h0);
    cudaGetSymbolAddress((void**)&h1, g_h1);
    cudaGetSymbolAddress((void**)&xp, g_xp);
    cudaGetSymbolAddress((void**)&hlast, g_hlast);
    cudaGetSymbolAddress((void**)&wt, g_wt);
    cudaGetSymbolAddress((void**)&bsv, g_bs);

    const int PGRID = B_ * (S_ / PST);   // 16384
    const int PSMEM = (64 * 68 + 64 * 256) * sizeof(float);

    cudaFuncSetAttribute(proj_kernel,
                         cudaFuncAttributeMaxDynamicSharedMemorySize, PSMEM);

    recur_kernel<true,  false><<<NCTA, 512>>>(x, Wih0, Whh0, bih0, bhh0, h0);

    wt_kernel<<<64, 256>>>(Wih1, bih1, bhh1, wt, bsv);
    proj_kernel<<<PGRID, 256, PSMEM>>>(h0, wt, bsv, xp);
    recur_kernel<false, false><<<NCTA, 512>>>(xp, nullptr, Whh1, nullptr, nullptr, h1);

    wt_kernel<<<64, 256>>>(Wih2, bih2, bhh2, wt, bsv);
    proj_kernel<<<PGRID, 256, PSMEM>>>(h1, wt, bsv, xp);
    recur_kernel<false, true><<<NCTA, 512>>>(xp, nullptr, Whh2, nullptr, nullptr, hlast);

    fc_kernel<<<(B_ + 255) / 256, 256>>>(hlast, fc_w, fc_b, out);
}

// round 12
// speedup vs baseline: 2.7567x; 1.2543x over previous
#include <cuda_runtime.h>
#include <cstddef>

typedef unsigned long long ull;

#define B_   512
#define S_   2048
#define H_   64
#define GB   4                  // batch per recurrent CTA
#define NCTA (B_ / GB)          // 128 CTAs -> 1 per SM
#define PST  64                 // proj s-tile

// Scratch (sanctioned __device__ globals)
__device__ float g_h0[(size_t)B_ * S_ * H_];
__device__ float g_h1[(size_t)B_ * S_ * H_];
__device__ float g_xp[(size_t)B_ * S_ * 4 * H_];
__device__ float g_hlast[B_ * H_];
__device__ float g_wt[64 * 256];     // transposed proj weights [k][r]
__device__ float g_bs[256];          // bih + bhh

struct alignas(16) UPair { ull lo, hi; };

__device__ __forceinline__ float ex2a(float x) {
    float y; asm("ex2.approx.ftz.f32 %0, %1;" : "=f"(y) : "f"(x)); return y;
}
__device__ __forceinline__ float rcpa(float x) {
    float y; asm("rcp.approx.ftz.f32 %0, %1;" : "=f"(y) : "f"(x)); return y;
}
__device__ __forceinline__ float sigf(float z) {
    return rcpa(1.0f + ex2a(-1.4426950408889634f * z));
}
__device__ __forceinline__ float tanha(float z) {
    return 1.0f - 2.0f * rcpa(1.0f + ex2a(2.8853900817779268f * z));
}
__device__ __forceinline__ ull ffma2(ull a, ull b, ull c) {
    ull d;
    asm("fma.rn.f32x2 %0, %1, %2, %3;" : "=l"(d) : "l"(a), "l"(b), "l"(c));
    return d;
}
__device__ __forceinline__ float hadd2(ull v) {
    float lo, hi;
    asm("mov.b64 {%0, %1}, %2;" : "=f"(lo), "=f"(hi) : "l"(v));
    return lo + hi;
}
__device__ __forceinline__ ull pack2(float lo, float hi) {
    ull d; asm("mov.b64 %0, {%1, %2};" : "=l"(d) : "f"(lo), "f"(hi)); return d;
}
__device__ __forceinline__ void unpack2(ull v, float& lo, float& hi) {
    asm("mov.b64 {%0, %1}, %2;" : "=f"(lo), "=f"(hi) : "l"(v));
}
__device__ __forceinline__ float shflb(float v, int x) {
    float r;
    asm("shfl.sync.bfly.b32 %0, %1, %2, 0x1F, 0xFFFFFFFF;"
        : "=r"(*(unsigned*)&r) : "r"(*(unsigned*)&v), "r"(x));
    return r;
}
// named barrier: id uniform per warp, count = participating threads
__device__ __forceinline__ void barn(int id, int cnt) {
    asm volatile("bar.sync %0, %1;" :: "r"(id), "r"(cnt) : "memory");
}

// ---------------------------------------------------------------------------
// Weight transpose + bias fold (one-time per layer, tiny).
// ---------------------------------------------------------------------------
__global__ void wt_kernel(const float* __restrict__ W,
                          const float* __restrict__ bih,
                          const float* __restrict__ bhh,
                          float* __restrict__ Wt,
                          float* __restrict__ bs)
{
    const int r = threadIdx.x;
    const int k = blockIdx.x;
    Wt[k * 256 + r] = W[r * 64 + k];
    if (k == 0) bs[r] = bih[r] + bhh[r];
}

// ---------------------------------------------------------------------------
// Outer-product proj GEMM (round-7 design, unchanged — measured good).
// ---------------------------------------------------------------------------
__global__ void __launch_bounds__(256, 2)
proj_kernel(const float* __restrict__ in,
            const float* __restrict__ Wt,
            const float* __restrict__ bs,
            float* __restrict__ out)
{
    extern __shared__ float sm[];
    float* xT = sm;                 // [64][68]
    float* ws = sm + 64 * 68;       // [64][256]

    const int tid = threadIdx.x;
    const int rg  = tid & 15;
    const int sg  = tid >> 4;
    const int stile = blockIdx.x & (S_ / PST - 1);
    const int b     = blockIdx.x / (S_ / PST);
    const size_t base = (size_t)b * S_ + (size_t)stile * PST;

    {
        const float4* gw = reinterpret_cast<const float4*>(Wt);
        float4* sw = reinterpret_cast<float4*>(ws);
        for (int i = tid; i < 64 * 256 / 4; i += 256) sw[i] = gw[i];
    }
    {
        const int sL = tid & 63;
        const int kq = tid >> 6;
        const float4* gin = reinterpret_cast<const float4*>(in + (base + sL) * H_);
#pragma unroll
        for (int it = 0; it < 4; ++it) {
            const int k4 = kq * 4 + it;
            const float4 v = gin[k4];
            xT[(4 * k4 + 0) * 68 + sL] = v.x;
            xT[(4 * k4 + 1) * 68 + sL] = v.y;
            xT[(4 * k4 + 2) * 68 + sL] = v.z;
            xT[(4 * k4 + 3) * 68 + sL] = v.w;
        }
    }
    __syncthreads();

    const UPair*  wsp = reinterpret_cast<const UPair*>(ws);
    const float4* xT4 = reinterpret_cast<const float4*>(xT);

    ull acc[4][4][2];
#pragma unroll
    for (int s = 0; s < 4; ++s)
#pragma unroll
        for (int j = 0; j < 4; ++j) { acc[s][j][0] = 0ull; acc[s][j][1] = 0ull; }

#pragma unroll 4
    for (int k = 0; k < 64; ++k) {
        const UPair w0 = wsp[k * 64 + rg];
        const UPair w1 = wsp[k * 64 + 16 + rg];
        const UPair w2 = wsp[k * 64 + 32 + rg];
        const UPair w3 = wsp[k * 64 + 48 + rg];
        const float4 av = xT4[k * 17 + sg];
        ull ar[4] = {pack2(av.x, av.x), pack2(av.y, av.y),
                     pack2(av.z, av.z), pack2(av.w, av.w)};
#pragma unroll
        for (int s = 0; s < 4; ++s) {
            acc[s][0][0] = ffma2(w0.lo, ar[s], acc[s][0][0]);
            acc[s][0][1] = ffma2(w0.hi, ar[s], acc[s][0][1]);
            acc[s][1][0] = ffma2(w1.lo, ar[s], acc[s][1][0]);
            acc[s][1][1] = ffma2(w1.hi, ar[s], acc[s][1][1]);
            acc[s][2][0] = ffma2(w2.lo, ar[s], acc[s][2][0]);
            acc[s][2][1] = ffma2(w2.hi, ar[s], acc[s][2][1]);
            acc[s][3][0] = ffma2(w3.lo, ar[s], acc[s][3][0]);
            acc[s][3][1] = ffma2(w3.hi, ar[s], acc[s][3][1]);
        }
    }

    float4 bv[4];
#pragma unroll
    for (int j = 0; j < 4; ++j)
        bv[j] = reinterpret_cast<const float4*>(bs)[16 * j + rg];
#pragma unroll
    for (int s = 0; s < 4; ++s) {
        const size_t srow = base + 4 * sg + s;
        float4* op = reinterpret_cast<float4*>(out + srow * 256);
#pragma unroll
        for (int j = 0; j < 4; ++j) {
            float x0, x1, x2, x3;
            unpack2(acc[s][j][0], x0, x1);
            unpack2(acc[s][j][1], x2, x3);
            float4 o;
            o.x = x0 + bv[j].x; o.y = x1 + bv[j].y;
            o.z = x2 + bv[j].z; o.w = x3 + bv[j].w;
            op[16 * j + rg] = o;
        }
    }
}

// ---------------------------------------------------------------------------
// Recurrent kernel (R7 mapping) with per-batch-pair NAMED BARRIERS.
// 256 threads. Warps 0-3 own batches (bp=0,1); warps 4-7 own (2,3).
// The two groups share no per-step state -> bar.sync (1+grp),128 instead of
// a CTA-wide barrier. Each SMSP holds one warp from each group, so a group
// stalled in its serial tail no longer blocks the other group's issue.
// ---------------------------------------------------------------------------
template <bool L0, bool LAST_ONLY>
__global__ void __launch_bounds__(256, 1)
recur_kernel(const float* __restrict__ xin,   // L0: x[B][S][4]; else z[B][S][256]
             const float* __restrict__ Wih,
             const float* __restrict__ Whh,
             const float* __restrict__ bih,
             const float* __restrict__ bhh,
             float* __restrict__ out)
{
    __shared__ __align__(16) float hb[2][GB * H_];

    const int tid = threadIdx.x;
    const int w   = tid >> 5;
    const int l   = tid & 31;
    const int p   = l & 1;
    const int uu  = (w & 3) * 16 + (l >> 1);
    const int grp = w >> 2;             // 0: batches 0,1   1: batches 2,3
    const int bp  = grp * 2;
    const int b0  = blockIdx.x * GB;
    const int rowA = uu + p * 128;
    const int rowB = rowA + 64;
    const int barid = 1 + grp;          // named barrier id (warp-uniform)

    ull wA[32], wB[32];
    {
        const ull* pa = reinterpret_cast<const ull*>(Whh + rowA * H_);
        const ull* pb = reinterpret_cast<const ull*>(Whh + rowB * H_);
#pragma unroll
        for (int k = 0; k < 32; ++k) { wA[k] = pa[k]; wB[k] = pb[k]; }
    }

    const float mA = p ? 2.8853900817779268f : -1.4426950408889634f;
    const float sA = p ? -2.0f : 1.0f;
    const float dA = p ? 1.0f : 0.0f;

    float biasA = 0.0f, biasB = 0.0f;
    ull wxA0 = 0, wxA1 = 0, wxB0 = 0, wxB1 = 0;
    const float4 *xq0 = nullptr, *xq1 = nullptr;
    const float *zp0 = nullptr, *zp1 = nullptr;
    float4 x0, x1; float za0 = 0, zb0 = 0, za1 = 0, zb1 = 0;

    if constexpr (L0) {
        biasA = bih[rowA] + bhh[rowA];
        biasB = bih[rowB] + bhh[rowB];
        const ull* wia = reinterpret_cast<const ull*>(Wih + rowA * 4);
        const ull* wib = reinterpret_cast<const ull*>(Wih + rowB * 4);
        wxA0 = wia[0]; wxA1 = wia[1];
        wxB0 = wib[0]; wxB1 = wib[1];
        xq0 = reinterpret_cast<const float4*>(xin + (size_t)(b0 + bp) * S_ * 4);
        xq1 = reinterpret_cast<const float4*>(xin + (size_t)(b0 + bp + 1) * S_ * 4);
        x0 = xq0[0]; x1 = xq1[0];
    } else {
        zp0 = xin + ((size_t)(b0 + bp)) * S_ * 256 + rowA;
        zp1 = xin + ((size_t)(b0 + bp + 1)) * S_ * 256 + rowA;
        za0 = zp0[0];  zb0 = zp0[64];
        za1 = zp1[0];  zb1 = zp1[64];
    }

    float c0 = 0.0f, c1 = 0.0f;
    for (int i = tid; i < GB * H_; i += 256) hb[1][i] = 0.0f;
    __syncthreads();   // one-time init barrier (CTA-wide)

    for (int t = 0; t < S_; ++t) {
        const UPair* v0 = reinterpret_cast<const UPair*>(hb[(t + 1) & 1] + bp * H_);
        const UPair* v1 = reinterpret_cast<const UPair*>(hb[(t + 1) & 1] + (bp + 1) * H_);

        float4 nx0, nx1;
        float nza0 = 0, nzb0 = 0, nza1 = 0, nzb1 = 0;
        if (t + 1 < S_) {
            if constexpr (L0) {
                nx0 = xq0[t + 1]; nx1 = xq1[t + 1];
            } else {
                const size_t o = (size_t)(t + 1) * 256;
                nza0 = zp0[o]; nzb0 = zp0[o + 64];
                nza1 = zp1[o]; nzb1 = zp1[o + 64];
            }
        }

        ull A0 = 0ull, B0 = 0ull, A1 = 0ull, B1 = 0ull;
#pragma unroll
        for (int k = 0; k < 16; ++k) {
            const ull wal = wA[2 * k], wah = wA[2 * k + 1];
            const ull wbl = wB[2 * k], wbh = wB[2 * k + 1];
            const UPair a0 = v0[k];
            const UPair a1 = v1[k];
            A0 = ffma2(wal, a0.lo, A0); A0 = ffma2(wah, a0.hi, A0);
            B0 = ffma2(wbl, a0.lo, B0); B0 = ffma2(wbh, a0.hi, B0);
            A1 = ffma2(wal, a1.lo, A1); A1 = ffma2(wah, a1.hi, A1);
            B1 = ffma2(wbl, a1.lo, B1); B1 = ffma2(wbh, a1.hi, B1);
        }
        float zA0, zB0, zA1, zB1;
        if constexpr (L0) {
            A0 = ffma2(wxA0, pack2(x0.x, x0.y), A0); A0 = ffma2(wxA1, pack2(x0.z, x0.w), A0);
            B0 = ffma2(wxB0, pack2(x0.x, x0.y), B0); B0 = ffma2(wxB1, pack2(x0.z, x0.w), B0);
            A1 = ffma2(wxA0, pack2(x1.x, x1.y), A1); A1 = ffma2(wxA1, pack2(x1.z, x1.w), A1);
            B1 = ffma2(wxB0, pack2(x1.x, x1.y), B1); B1 = ffma2(wxB1, pack2(x1.z, x1.w), B1);
            zA0 = hadd2(A0) + biasA; zB0 = hadd2(B0) + biasB;
            zA1 = hadd2(A1) + biasA; zB1 = hadd2(B1) + biasB;
        } else {
            zA0 = hadd2(A0) + za0; zB0 = hadd2(B0) + zb0;
            zA1 = hadd2(A1) + za1; zB1 = hadd2(B1) + zb1;
        }

        const float aA0 = sA * rcpa(1.0f + ex2a(mA * zA0)) + dA;
        const float aA1 = sA * rcpa(1.0f + ex2a(mA * zA1)) + dA;
        const float aB0 = sigf(zB0);
        const float aB1 = sigf(zB1);

        const float oA0 = shflb(aA0, 1);
        const float oB0 = shflb(aB0, 1);
        const float oA1 = shflb(aA1, 1);
        const float oB1 = shflb(aB1, 1);
        const float gi0 = p ? oA0 : aA0;
        const float gf0 = p ? oB0 : aB0;
        const float gg0 = p ? aA0 : oA0;
        const float go0 = p ? aB0 : oB0;
        const float gi1 = p ? oA1 : aA1;
        const float gf1 = p ? oB1 : aB1;
        const float gg1 = p ? aA1 : oA1;
        const float go1 = p ? aB1 : oB1;

        c0 = gf0 * c0 + gi0 * gg0;
        c1 = gf1 * c1 + gi1 * gg1;
        const float h0v = go0 * tanha(c0);
        const float h1v = go1 * tanha(c1);

        if (p == 0) {
            hb[t & 1][bp * H_ + uu]       = h0v;
            hb[t & 1][(bp + 1) * H_ + uu] = h1v;
            if constexpr (LAST_ONLY) {
                if (t == S_ - 1) {
                    out[(b0 + bp) * H_ + uu]     = h0v;
                    out[(b0 + bp + 1) * H_ + uu] = h1v;
                }
            } else {
                out[((size_t)(b0 + bp) * S_ + t) * H_ + uu]     = h0v;
                out[((size_t)(b0 + bp + 1) * S_ + t) * H_ + uu] = h1v;
            }
        }

        za0 = nza0; zb0 = nzb0; za1 = nza1; zb1 = nzb1;
        if constexpr (L0) { x0 = nx0; x1 = nx1; }

        barn(barid, 128);   // group-local barrier: decouples the two halves
    }
}

// out[b] = h_last[b] @ fc_w^T + fc_b
__global__ void fc_kernel(const float* __restrict__ hbuf,
                          const float* __restrict__ fw,
                          const float* __restrict__ fb,
                          float* __restrict__ outp)
{
    int b = blockIdx.x * blockDim.x + threadIdx.x;
    if (b >= B_) return;
    const float* h = hbuf + (size_t)b * H_;
    float a0 = fb[0], a1 = fb[1];
#pragma unroll
    for (int k = 0; k < H_; ++k) {
        float hv = h[k];
        a0 += hv * fw[k];
        a1 += hv * fw[H_ + k];
    }
    outp[b * 2 + 0] = a0;
    outp[b * 2 + 1] = a1;
}

extern "C" void kernel_launch(void* const* d_in, const int* in_sizes, int n_in,
                              void* d_out, int out_size)
{
    const float* x    = (const float*)d_in[0];
    const float* Wih0 = (const float*)d_in[1];
    const float* Whh0 = (const float*)d_in[2];
    const float* bih0 = (const float*)d_in[3];
    const float* bhh0 = (const float*)d_in[4];
    const float* Wih1 = (const float*)d_in[5];
    const float* Whh1 = (const float*)d_in[6];
    const float* bih1 = (const float*)d_in[7];
    const float* bhh1 = (const float*)d_in[8];
    const float* Wih2 = (const float*)d_in[9];
    const float* Whh2 = (const float*)d_in[10];
    const float* bih2 = (const float*)d_in[11];
    const float* bhh2 = (const float*)d_in[12];
    const float* fc_w = (const float*)d_in[13];
    const float* fc_b = (const float*)d_in[14];
    float* out = (float*)d_out;

    float *h0, *h1, *xp, *hlast, *wt, *bsv;
    cudaGetSymbolAddress((void**)&h0, g_h0);
    cudaGetSymbolAddress((void**)&h1, g_h1);
    cudaGetSymbolAddress((void**)&xp, g_xp);
    cudaGetSymbolAddress((void**)&hlast, g_hlast);
    cudaGetSymbolAddress((void**)&wt, g_wt);
    cudaGetSymbolAddress((void**)&bsv, g_bs);

    const int PGRID = B_ * (S_ / PST);   // 16384
    const int PSMEM = (64 * 68 + 64 * 256) * sizeof(float);

    cudaFuncSetAttribute(proj_kernel,
                         cudaFuncAttributeMaxDynamicSharedMemorySize, PSMEM);

    recur_kernel<true,  false><<<NCTA, 256>>>(x, Wih0, Whh0, bih0, bhh0, h0);

    wt_kernel<<<64, 256>>>(Wih1, bih1, bhh1, wt, bsv);
    proj_kernel<<<PGRID, 256, PSMEM>>>(h0, wt, bsv, xp);
    recur_kernel<false, false><<<NCTA, 256>>>(xp, nullptr, Whh1, nullptr, nullptr, h1);

    wt_kernel<<<64, 256>>>(Wih2, bih2, bhh2, wt, bsv);
    proj_kernel<<<PGRID, 256, PSMEM>>>(h1, wt, bsv, xp);
    recur_kernel<false, true><<<NCTA, 256>>>(xp, nullptr, Whh2, nullptr, nullptr, hlast);

    fc_kernel<<<(B_ + 255) / 256, 256>>>(hlast, fc_w, fc_b, out);
}